// round 1
// baseline (speedup 1.0000x reference)
#include <cuda_runtime.h>
#include <cstdint>
#include <math.h>

#define B_TOT 32768
#define KNBR  32
#define D     128
#define T     512
#define NPAIR (B_TOT / 2)

// smem layout (float offsets)
#define OFF_HN    0        // 2 * 2*32*128 = 16384 (double-buffered pair of h_nei tiles)
#define OFF_HE    16384    // 2 * 2*128   = 512   (double-buffered h_ego pair)
#define OFF_VS    16896    // 256  (v_ego | v_nbr)
#define OFF_AGG   17152    // 256  (packed: agg[2*d + b])
#define OFF_EGO2  17408    // 256  (packed: ego[2*d + b])
#define OFF_RED   17664    // 1024 (float2[4][128])
#define OFF_BS    18688    // 128  (b_self)
#define OFF_LOG   18816    // 64
#define OFF_ATT   18880    // 64
#define OFF_CEGO  18944    // 4
#define OFF_MSK   18948    // 128 ints (double-buffered masks)
#define SMEM_FLOATS 19080
#define SMEM_BYTES (SMEM_FLOATS * 4)

__device__ float g_v[2 * D];   // [0:128) = v_ego = W_msg^T a_ego, [128:256) = v_nbr

// ---------------- prologue: v = W_msg^T @ a ----------------
__global__ void prep_kernel(const float* __restrict__ Wmsg,
                            const float* __restrict__ Wattn) {
    int d = threadIdx.x;   // 128 threads
    float ve = 0.f, vn = 0.f;
    #pragma unroll 8
    for (int e = 0; e < D; e++) {
        float w = Wmsg[e * D + d];           // coalesced across d
        ve = fmaf(Wattn[e], w, ve);
        vn = fmaf(Wattn[D + e], w, vn);
    }
    g_v[d] = ve;
    g_v[D + d] = vn;
}

// ---------------- cp.async helpers ----------------
__device__ __forceinline__ void cp16(uint32_t dst, const void* src) {
    asm volatile("cp.async.ca.shared.global [%0], [%1], 16;" :: "r"(dst), "l"(src));
}
__device__ __forceinline__ void cp_commit() { asm volatile("cp.async.commit_group;"); }
__device__ __forceinline__ void cp_wait1()  { asm volatile("cp.async.wait_group 1;" ::: "memory"); }
__device__ __forceinline__ void cp_waitall(){ asm volatile("cp.async.wait_all;" ::: "memory"); }

__device__ __forceinline__ void prefetch_pair(int p, int buf, int tid, uint32_t smem_u32,
                                              const float* __restrict__ h_nei,
                                              const float* __restrict__ h_ego,
                                              const int*   __restrict__ nbr_mask) {
    const float* src = h_nei + (size_t)p * (2 * KNBR * D);       // 8192 floats
    uint32_t hdst = smem_u32 + (uint32_t)(OFF_HN + buf * 8192) * 4u;
    #pragma unroll
    for (int i = 0; i < 4; i++) {                                 // 2048 float4 total
        int idx = tid + i * T;
        cp16(hdst + (uint32_t)idx * 16u, src + idx * 4);
    }
    if (tid < 64)
        cp16(smem_u32 + (uint32_t)(OFF_HE + buf * 256 + tid * 4) * 4u,
             h_ego + (size_t)p * 256 + tid * 4);
    if (tid < 16)
        cp16(smem_u32 + (uint32_t)(OFF_MSK + buf * 64 + tid * 4) * 4u,
             nbr_mask + (size_t)p * 64 + tid * 4);
}

// ---------------- main fused kernel ----------------
__global__ void __launch_bounds__(T, 1)
gat_kernel(const float* __restrict__ h_ego, const float* __restrict__ h_nei,
           const int*   __restrict__ nbr_mask,
           const float* __restrict__ Wmsg, const float* __restrict__ Wself,
           const float* __restrict__ bself, float* __restrict__ out) {
    extern __shared__ float sm[];
    float* hn    = sm + OFF_HN;
    float* he    = sm + OFF_HE;
    float* vs    = sm + OFF_VS;
    float* agg   = sm + OFF_AGG;
    float* ego2  = sm + OFF_EGO2;
    float* red   = sm + OFF_RED;
    float* bs    = sm + OFF_BS;
    float* logit = sm + OFF_LOG;
    float* attn  = sm + OFF_ATT;
    float* cego  = sm + OFF_CEGO;
    int*   msks  = (int*)(sm + OFF_MSK);

    const int tid  = threadIdx.x;
    const int lane = tid & 31;
    const int warp = tid >> 5;
    const int e    = tid & 127;
    const int g    = tid >> 7;            // 0..3
    const int d0   = (g & 1) * 64;

    // cache a 64-float W slice in registers (groups 0,1: W_msg; 2,3: W_self)
    const float* Wsrc = (g < 2) ? Wmsg : Wself;
    float wreg[64];
    #pragma unroll
    for (int j = 0; j < 64; j += 4) {
        float4 t4 = *(const float4*)&Wsrc[e * D + d0 + j];
        wreg[j] = t4.x; wreg[j + 1] = t4.y; wreg[j + 2] = t4.z; wreg[j + 3] = t4.w;
    }
    if (tid < 2 * D) vs[tid] = g_v[tid];
    if (tid >= 256 && tid < 256 + D) bs[tid - 256] = bself[tid - 256];
    __syncthreads();
    const float4 vE = *(const float4*)&vs[lane * 4];
    const float4 vN = *(const float4*)&vs[D + lane * 4];

    const uint32_t smem_u32 = (uint32_t)__cvta_generic_to_shared(sm);
    const float NEG_INF = __int_as_float(0xff800000);

    int p = blockIdx.x;
    int s = 0;
    if (p < NPAIR) prefetch_pair(p, 0, tid, smem_u32, h_nei, h_ego, nbr_mask);
    cp_commit();

    for (; p < NPAIR; p += gridDim.x) {
        int pn = p + gridDim.x;
        if (pn < NPAIR) prefetch_pair(pn, s ^ 1, tid, smem_u32, h_nei, h_ego, nbr_mask);
        cp_commit();
        cp_wait1();
        __syncthreads();

        const float* hnb = &hn[s * 8192];
        const float* heb = &he[s * 256];

        // ---- phase A: c_ego per row (warps 0,1), pack ego (threads 256..511) ----
        if (warp < 2) {
            float4 x = *(const float4*)&heb[warp * D + lane * 4];
            float part = x.x * vE.x + x.y * vE.y + x.z * vE.z + x.w * vE.w;
            #pragma unroll
            for (int o = 16; o > 0; o >>= 1) part += __shfl_xor_sync(0xffffffffu, part, o);
            if (lane == 0) cego[warp] = part;
        }
        if (tid >= 256) {
            int bl = (tid >> 7) & 1;
            int dd = tid & 127;
            ego2[2 * dd + bl] = heb[bl * D + dd];
        }
        __syncthreads();

        // ---- phase B: 64 logits (one warp-dot each) ----
        #pragma unroll
        for (int j = 0; j < 4; j++) {
            int m  = warp * 4 + j;
            int bl = m >> 5, k = m & 31;
            float4 x = *(const float4*)&hnb[bl * 4096 + k * D + lane * 4];
            float part = x.x * vN.x + x.y * vN.y + x.z * vN.z + x.w * vN.w;
            #pragma unroll
            for (int o = 16; o > 0; o >>= 1) part += __shfl_xor_sync(0xffffffffu, part, o);
            if (lane == 0) {
                float lg = part + cego[bl];
                lg = (lg > 0.f) ? lg : 0.2f * lg;              // leaky_relu(0.2)
                logit[m] = (msks[s * 64 + m] > 0) ? lg : NEG_INF;
            }
        }
        __syncthreads();

        // ---- phase C: masked softmax over K (warps 0,1) ----
        if (warp < 2) {
            float x = logit[warp * KNBR + lane];
            float mx = x;
            #pragma unroll
            for (int o = 16; o > 0; o >>= 1) mx = fmaxf(mx, __shfl_xor_sync(0xffffffffu, mx, o));
            float ee = (x == NEG_INF) ? 0.f : __expf(x - mx);
            float ss = ee;
            #pragma unroll
            for (int o = 16; o > 0; o >>= 1) ss += __shfl_xor_sync(0xffffffffu, ss, o);
            attn[warp * KNBR + lane] = (ss > 0.f) ? (ee / ss) : 0.f;
        }
        __syncthreads();

        // ---- phase D: h_agg[b,d] = sum_k attn[k] * h_nei[b,k,d] ----
        if (tid < 256) {
            int bl = tid >> 7, dd = tid & 127;
            float av = attn[bl * KNBR + lane];
            const float* hb = &hnb[bl * 4096];
            float a = 0.f;
            #pragma unroll
            for (int k = 0; k < KNBR; k++) {
                float ak = __shfl_sync(0xffffffffu, av, k);
                a = fmaf(ak, hb[k * D + dd], a);
            }
            agg[2 * dd + bl] = a;
        }
        __syncthreads();

        // ---- phase E: out = tanh(agg @ Wmsg^T + ego @ Wself^T + b)  (FFMA2 packed) ----
        {
            const unsigned long long* xq =
                (const unsigned long long*)((g < 2) ? agg : ego2);
            unsigned long long acc = 0ull;
            #pragma unroll
            for (int j = 0; j < 64; j += 2) {
                ulonglong2 xx = *(const ulonglong2*)&xq[d0 + j];   // {b0,b1} for 2 dims
                unsigned long long w0, w1;
                unsigned int wa = __float_as_uint(wreg[j]);
                unsigned int wb = __float_as_uint(wreg[j + 1]);
                asm("mov.b64 %0, {%1,%1};" : "=l"(w0) : "r"(wa));
                asm("mov.b64 %0, {%1,%1};" : "=l"(w1) : "r"(wb));
                asm("fma.rn.f32x2 %0, %1, %2, %3;" : "=l"(acc) : "l"(w0), "l"(xx.x), "l"(acc));
                asm("fma.rn.f32x2 %0, %1, %2, %3;" : "=l"(acc) : "l"(w1), "l"(xx.y), "l"(acc));
            }
            *(unsigned long long*)&red[(g * 128 + e) * 2] = acc;
        }
        __syncthreads();
        if (tid < D) {
            float2 r0 = *(float2*)&red[(0 * 128 + tid) * 2];
            float2 r1 = *(float2*)&red[(1 * 128 + tid) * 2];
            float2 r2 = *(float2*)&red[(2 * 128 + tid) * 2];
            float2 r3 = *(float2*)&red[(3 * 128 + tid) * 2];
            float bb = bs[tid];
            float o0 = tanhf(r0.x + r1.x + r2.x + r3.x + bb);
            float o1 = tanhf(r0.y + r1.y + r2.y + r3.y + bb);
            size_t row = (size_t)(2 * p) * D;
            out[row + tid]     = o0;
            out[row + D + tid] = o1;
        }
        s ^= 1;
    }
    cp_waitall();
}

// ---------------- launch ----------------
extern "C" void kernel_launch(void* const* d_in, const int* in_sizes, int n_in,
                              void* d_out, int out_size) {
    const float* h_ego  = (const float*)d_in[0];
    const float* h_nei  = (const float*)d_in[1];
    const int*   nmask  = (const int*)  d_in[2];
    const float* Wmsg   = (const float*)d_in[3];
    const float* Wattn  = (const float*)d_in[4];
    const float* Wself  = (const float*)d_in[5];
    const float* bself  = (const float*)d_in[6];
    float* out = (float*)d_out;

    int sms = 0;
    cudaDeviceGetAttribute(&sms, cudaDevAttrMultiProcessorCount, 0);
    if (sms <= 0) sms = 148;

    cudaFuncSetAttribute(gat_kernel, cudaFuncAttributeMaxDynamicSharedMemorySize, SMEM_BYTES);

    prep_kernel<<<1, D>>>(Wmsg, Wattn);
    gat_kernel<<<sms, T, SMEM_BYTES>>>(h_ego, h_nei, nmask, Wmsg, Wself, bself, out);
}

// round 2
// speedup vs baseline: 1.0747x; 1.0747x over previous
#include <cuda_runtime.h>
#include <cstdint>
#include <math.h>

#define KNBR  32
#define D     128
#define T     512
#define B_TOT 32768
#define NPAIR (B_TOT / 2)

__device__ float g_v[2 * D];   // [0:128) v_ego = W_msg^T a_ego, [128:256) v_nbr

// ---------------- prologue: v = W_msg^T @ a ----------------
__global__ void prep_kernel(const float* __restrict__ Wmsg,
                            const float* __restrict__ Wattn) {
    int d = threadIdx.x;   // 128 threads
    float ve = 0.f, vn = 0.f;
    #pragma unroll 8
    for (int e = 0; e < D; e++) {
        float w = Wmsg[e * D + d];
        ve = fmaf(Wattn[e], w, ve);
        vn = fmaf(Wattn[D + e], w, vn);
    }
    g_v[d] = ve;
    g_v[D + d] = vn;
}

// ---------------- register prefetch of one pair's inputs ----------------
__device__ __forceinline__ void prefetch(
    int p,
    const float* __restrict__ h_nei, const float* __restrict__ h_ego,
    const int*   __restrict__ nbr_mask,
    int bl, int kq, int warp, int lane, int m0,
    float4 xb[4], float4& eg, int& mk)
{
    const float4* src = (const float4*)(h_nei + ((size_t)p * 8192 + bl * 4096 + kq * 128)) + lane;
    xb[0] = __ldcs(src);
    xb[1] = __ldcs(src + 32);
    xb[2] = __ldcs(src + 64);
    xb[3] = __ldcs(src + 96);
    if (warp < 2)
        eg = __ldcs((const float4*)(h_ego + (size_t)p * 256 + warp * 128) + lane);
    if (lane < 4)
        mk = __ldg(nbr_mask + (size_t)p * 64 + m0 + lane);
}

// smem (static, ~12KB)
struct SmemT {
    float red[2048];   // phase D partials (float4/lane) ; reused as phase E acc2 (u64)
    float agg2[256];   // batch-packed: agg2[2*d + row]
    float ego2[256];   // batch-packed
    float vs[256];     // v_ego | v_nbr
    float logit[64];
    float attn[64];
    float cego[2];
};

__device__ __forceinline__ void body(
    int p, int pn, int G,
    const float* __restrict__ h_nei, const float* __restrict__ h_ego,
    const int*   __restrict__ nbr_mask, float* __restrict__ out,
    SmemT* sm,
    int tid, int lane, int warp, int g, int e, int d0, int bl, int kq, int m0,
    const float* wreg, float bb,
    float4 xb[4], float4& eg, int& mk,          // current (loaded)
    float4 xbn[4], float4& egn, int& mkn)       // next (prefetch target)
{
    const float NEG_INF = __int_as_float(0xff800000);

    // ---- prefetch next pair straight into registers ----
    if (pn < NPAIR)
        prefetch(pn, h_nei, h_ego, nbr_mask, bl, kq, warp, lane, m0, xbn, egn, mkn);

    // ---- phase A: ego dot + batch-packed ego stash (warps 0,1) ----
    if (warp < 2) {
        float4 vE = *(const float4*)&sm->vs[lane * 4];
        float pa = eg.x * vE.x + eg.y * vE.y + eg.z * vE.z + eg.w * vE.w;
        #pragma unroll
        for (int o = 16; o > 0; o >>= 1) pa += __shfl_xor_sync(0xffffffffu, pa, o);
        if (lane == 0) sm->cego[warp] = pa;
        int dd = lane * 4;
        sm->ego2[2 * (dd + 0) + warp] = eg.x;
        sm->ego2[2 * (dd + 1) + warp] = eg.y;
        sm->ego2[2 * (dd + 2) + warp] = eg.z;
        sm->ego2[2 * (dd + 3) + warp] = eg.w;
    }
    __syncthreads();   // B1

    // ---- phase B: 4 neighbor logits per warp, from registers ----
    {
        float4 vN = *(const float4*)&sm->vs[D + lane * 4];
        float p0 = xb[0].x * vN.x + xb[0].y * vN.y + xb[0].z * vN.z + xb[0].w * vN.w;
        float p1 = xb[1].x * vN.x + xb[1].y * vN.y + xb[1].z * vN.z + xb[1].w * vN.w;
        float p2 = xb[2].x * vN.x + xb[2].y * vN.y + xb[2].z * vN.z + xb[2].w * vN.w;
        float p3 = xb[3].x * vN.x + xb[3].y * vN.y + xb[3].z * vN.z + xb[3].w * vN.w;
        #pragma unroll
        for (int o = 16; o > 0; o >>= 1) {
            p0 += __shfl_xor_sync(0xffffffffu, p0, o);
            p1 += __shfl_xor_sync(0xffffffffu, p1, o);
            p2 += __shfl_xor_sync(0xffffffffu, p2, o);
            p3 += __shfl_xor_sync(0xffffffffu, p3, o);
        }
        if (lane < 4) {
            float myv = (lane == 0) ? p0 : (lane == 1) ? p1 : (lane == 2) ? p2 : p3;
            float lg = myv + sm->cego[bl];
            lg = (lg > 0.f) ? lg : 0.2f * lg;              // leaky_relu(0.2)
            sm->logit[m0 + lane] = (mk > 0) ? lg : NEG_INF;
        }
    }
    __syncthreads();   // B2

    // ---- phase C: masked softmax over K (warps 0,1) ----
    if (warp < 2) {
        float x = sm->logit[warp * KNBR + lane];
        float mx = x;
        #pragma unroll
        for (int o = 16; o > 0; o >>= 1) mx = fmaxf(mx, __shfl_xor_sync(0xffffffffu, mx, o));
        float ee = (x == NEG_INF) ? 0.f : __expf(x - mx);
        float ss = ee;
        #pragma unroll
        for (int o = 16; o > 0; o >>= 1) ss += __shfl_xor_sync(0xffffffffu, ss, o);
        sm->attn[warp * KNBR + lane] = (ss > 0.f) ? (ee / ss) : 0.f;
    }
    __syncthreads();   // B3

    // ---- phase D: weighted partials from the SAME registers ----
    {
        float a0 = sm->attn[m0 + 0];
        float a1 = sm->attn[m0 + 1];
        float a2 = sm->attn[m0 + 2];
        float a3 = sm->attn[m0 + 3];
        float4 acc;
        acc.x = fmaf(a3, xb[3].x, fmaf(a2, xb[2].x, fmaf(a1, xb[1].x, a0 * xb[0].x)));
        acc.y = fmaf(a3, xb[3].y, fmaf(a2, xb[2].y, fmaf(a1, xb[1].y, a0 * xb[0].y)));
        acc.z = fmaf(a3, xb[3].z, fmaf(a2, xb[2].z, fmaf(a1, xb[1].z, a0 * xb[0].z)));
        acc.w = fmaf(a3, xb[3].w, fmaf(a2, xb[2].w, fmaf(a1, xb[1].w, a0 * xb[0].w)));
        ((float4*)sm->red)[warp * 32 + lane] = acc;
    }
    __syncthreads();   // B4

    // ---- cross-warp reduce (8 partials per (row,dim)) ----
    if (tid < 256) {
        int bl2 = tid >> 7, dd = tid & 127;
        const float* rb = &sm->red[bl2 * 8 * 128 + dd];
        float a = rb[0] + rb[128] + rb[256] + rb[384] +
                  rb[512] + rb[640] + rb[768] + rb[896];
        sm->agg2[2 * dd + bl2] = a;
    }
    __syncthreads();   // B5

    // ---- phase E: out = tanh([agg|ego] @ [Wmsg|Wself]^T + b), FFMA2 packed ----
    {
        const unsigned long long* xq =
            (const unsigned long long*)((g < 2) ? sm->agg2 : sm->ego2);
        unsigned long long acc = 0ull;
        #pragma unroll
        for (int j = 0; j < 64; j += 2) {
            ulonglong2 xx = *(const ulonglong2*)&xq[d0 + j];
            unsigned long long w0, w1;
            unsigned int wa = __float_as_uint(wreg[j]);
            unsigned int wb = __float_as_uint(wreg[j + 1]);
            asm("mov.b64 %0, {%1,%1};" : "=l"(w0) : "r"(wa));
            asm("mov.b64 %0, {%1,%1};" : "=l"(w1) : "r"(wb));
            asm("fma.rn.f32x2 %0, %1, %2, %3;" : "=l"(acc) : "l"(w0), "l"(xx.x), "l"(acc));
            asm("fma.rn.f32x2 %0, %1, %2, %3;" : "=l"(acc) : "l"(w1), "l"(xx.y), "l"(acc));
        }
        ((unsigned long long*)sm->red)[g * 128 + e] = acc;
    }
    __syncthreads();   // B6

    if (tid < D) {
        const float2* r = (const float2*)sm->red;
        float2 r0 = r[0 * 128 + tid];
        float2 r1 = r[1 * 128 + tid];
        float2 r2 = r[2 * 128 + tid];
        float2 r3 = r[3 * 128 + tid];
        float o0 = tanhf(r0.x + r1.x + r2.x + r3.x + bb);
        float o1 = tanhf(r0.y + r1.y + r2.y + r3.y + bb);
        size_t row = (size_t)(2 * p) * D;
        out[row + tid]     = o0;
        out[row + D + tid] = o1;
    }
    // no trailing barrier needed: next iter's first smem writes are ordered by B1
}

__global__ void __launch_bounds__(T, 1)
gat_kernel(const float* __restrict__ h_ego, const float* __restrict__ h_nei,
           const int*   __restrict__ nbr_mask,
           const float* __restrict__ Wmsg, const float* __restrict__ Wself,
           const float* __restrict__ bself, float* __restrict__ out) {
    __shared__ SmemT sm;

    const int tid  = threadIdx.x;
    const int lane = tid & 31;
    const int warp = tid >> 5;
    const int g    = tid >> 7;            // 0..3
    const int e    = tid & 127;
    const int d0   = (g & 1) * 64;
    const int bl   = warp >> 3;           // which row of the pair this warp's k's belong to
    const int kq   = (warp & 7) * 4;      // first k index
    const int m0   = warp * 4;            // first logit slot (0..63)

    // W slice in registers (groups 0,1: W_msg; 2,3: W_self)
    const float* Wsrc = (g < 2) ? Wmsg : Wself;
    float wreg[64];
    #pragma unroll
    for (int j = 0; j < 64; j += 4) {
        float4 t4 = *(const float4*)&Wsrc[e * D + d0 + j];
        wreg[j] = t4.x; wreg[j + 1] = t4.y; wreg[j + 2] = t4.z; wreg[j + 3] = t4.w;
    }
    if (tid < 2 * D) sm.vs[tid] = g_v[tid];
    float bb = (tid < D) ? __ldg(bself + tid) : 0.f;
    __syncthreads();

    const int G = gridDim.x;
    int p = blockIdx.x;

    float4 xa[4], xc[4];
    float4 ega = {0,0,0,0}, egc = {0,0,0,0};
    int mka = 0, mkc = 0;

    if (p < NPAIR)
        prefetch(p, h_nei, h_ego, nbr_mask, bl, kq, warp, lane, m0, xa, ega, mka);

    while (p < NPAIR) {
        body(p, p + G, G, h_nei, h_ego, nbr_mask, out, &sm,
             tid, lane, warp, g, e, d0, bl, kq, m0, wreg, bb,
             xa, ega, mka, xc, egc, mkc);
        p += G;
        if (p >= NPAIR) break;
        body(p, p + G, G, h_nei, h_ego, nbr_mask, out, &sm,
             tid, lane, warp, g, e, d0, bl, kq, m0, wreg, bb,
             xc, egc, mkc, xa, ega, mka);
        p += G;
    }
}

// ---------------- launch ----------------
extern "C" void kernel_launch(void* const* d_in, const int* in_sizes, int n_in,
                              void* d_out, int out_size) {
    const float* h_ego  = (const float*)d_in[0];
    const float* h_nei  = (const float*)d_in[1];
    const int*   nmask  = (const int*)  d_in[2];
    const float* Wmsg   = (const float*)d_in[3];
    const float* Wattn  = (const float*)d_in[4];
    const float* Wself  = (const float*)d_in[5];
    const float* bself  = (const float*)d_in[6];
    float* out = (float*)d_out;

    int sms = 0;
    cudaDeviceGetAttribute(&sms, cudaDevAttrMultiProcessorCount, 0);
    if (sms <= 0) sms = 148;

    prep_kernel<<<1, D>>>(Wmsg, Wattn);
    gat_kernel<<<sms, T>>>(h_ego, h_nei, nmask, Wmsg, Wself, bself, out);
}

// round 3
// speedup vs baseline: 1.1356x; 1.0567x over previous
#include <cuda_runtime.h>
#include <cstdint>
#include <math.h>

#define KNBR  32
#define D     128
#define T     512
#define B_TOT 32768
#define NPAIR (B_TOT / 2)

// smem layout (float offsets)
#define OFF_HN    0        // 2 * 8192 (double-buffered pair of h_nei tiles)
#define OFF_HE    16384    // 2 * 256
#define OFF_MSK   16896    // 2 * 64 ints
#define OFF_VS    17024    // 256 (v_ego | v_nbr)
#define OFF_EGO2  17280    // 256 batch-packed ego
#define OFF_AGG2  17536    // 256 batch-packed agg
#define OFF_RED   17792    // 2048
#define OFF_LOG   19840    // 64
#define OFF_ATT   19904    // 64
#define SMEM_FLOATS 19968
#define SMEM_BYTES (SMEM_FLOATS * 4)

__device__ float g_v[2 * D];   // [0:128) v_ego = W_msg^T a_ego, [128:256) v_nbr

// ---------------- prologue: v = W_msg^T @ a ----------------
__global__ void prep_kernel(const float* __restrict__ Wmsg,
                            const float* __restrict__ Wattn) {
    int d = threadIdx.x;   // 128 threads
    float ve = 0.f, vn = 0.f;
    #pragma unroll 8
    for (int e = 0; e < D; e++) {
        float w = Wmsg[e * D + d];
        ve = fmaf(Wattn[e], w, ve);
        vn = fmaf(Wattn[D + e], w, vn);
    }
    g_v[d] = ve;
    g_v[D + d] = vn;
}

// ---------------- cp.async helpers ----------------
__device__ __forceinline__ void cp16(uint32_t dst, const void* src) {
    asm volatile("cp.async.cg.shared.global [%0], [%1], 16;" :: "r"(dst), "l"(src));
}
__device__ __forceinline__ void cp_commit() { asm volatile("cp.async.commit_group;"); }
__device__ __forceinline__ void cp_wait1()  { asm volatile("cp.async.wait_group 1;" ::: "memory"); }
__device__ __forceinline__ void cp_waitall(){ asm volatile("cp.async.wait_all;" ::: "memory"); }

__device__ __forceinline__ void prefetch_pair(int p, int buf, int tid, uint32_t smem_u32,
                                              const float* __restrict__ h_nei,
                                              const float* __restrict__ h_ego,
                                              const int*   __restrict__ nbr_mask) {
    const float* src = h_nei + (size_t)p * 8192;
    uint32_t hdst = smem_u32 + (uint32_t)(OFF_HN + buf * 8192) * 4u;
    #pragma unroll
    for (int i = 0; i < 4; i++) {
        int idx = tid + i * T;
        cp16(hdst + (uint32_t)idx * 16u, src + idx * 4);
    }
    if (tid < 64)
        cp16(smem_u32 + (uint32_t)(OFF_HE + buf * 256 + tid * 4) * 4u,
             h_ego + (size_t)p * 256 + tid * 4);
    if (tid < 16)
        cp16(smem_u32 + (uint32_t)(OFF_MSK + buf * 64 + tid * 4) * 4u,
             nbr_mask + (size_t)p * 64 + tid * 4);
}

// ---------------- main fused kernel ----------------
__global__ void __launch_bounds__(T, 1)
gat_kernel(const float* __restrict__ h_ego, const float* __restrict__ h_nei,
           const int*   __restrict__ nbr_mask,
           const float* __restrict__ Wmsg, const float* __restrict__ Wself,
           const float* __restrict__ bself, float* __restrict__ out) {
    extern __shared__ float sm[];
    float* hn    = sm + OFF_HN;
    float* he    = sm + OFF_HE;
    int*   msk   = (int*)(sm + OFF_MSK);
    float* vs    = sm + OFF_VS;
    float* ego2  = sm + OFF_EGO2;
    float* agg2  = sm + OFF_AGG2;
    float* red   = sm + OFF_RED;
    float* logit = sm + OFF_LOG;
    float* attn  = sm + OFF_ATT;

    const int tid  = threadIdx.x;
    const int lane = tid & 31;
    const int warp = tid >> 5;
    const int g    = tid >> 7;            // 0..3
    const int e    = tid & 127;
    const int d0   = (g & 1) * 64;
    const int bl   = warp >> 3;           // row of the pair for this warp's k's
    const int kq   = (warp & 7) * 4;      // first k
    const int m0   = warp * 4;            // first logit slot (0..63)

    // W slice in registers (groups 0,1: W_msg; 2,3: W_self) — the only pinned regs
    const float* Wsrc = (g < 2) ? Wmsg : Wself;
    float wreg[64];
    #pragma unroll
    for (int j = 0; j < 64; j += 4) {
        float4 t4 = *(const float4*)&Wsrc[e * D + d0 + j];
        wreg[j] = t4.x; wreg[j + 1] = t4.y; wreg[j + 2] = t4.z; wreg[j + 3] = t4.w;
    }
    if (tid < 2 * D) vs[tid] = g_v[tid];
    float bb = (tid < D) ? __ldg(bself + tid) : 0.f;
    __syncthreads();

    const uint32_t smem_u32 = (uint32_t)__cvta_generic_to_shared(sm);
    const float NEG_INF = __int_as_float(0xff800000);
    const int G = gridDim.x;

    int p = blockIdx.x;
    int s = 0;
    if (p < NPAIR) prefetch_pair(p, 0, tid, smem_u32, h_nei, h_ego, nbr_mask);
    cp_commit();

    for (; p < NPAIR; p += G, s ^= 1) {
        int pn = p + G;
        if (pn < NPAIR) prefetch_pair(pn, s ^ 1, tid, smem_u32, h_nei, h_ego, nbr_mask);
        cp_commit();
        cp_wait1();
        __syncthreads();   // B0: buffer s ready for everyone

        const float* hnb  = &hn[s * 8192];
        const float* heb  = &he[s * 256];
        const int*   mskb = &msk[s * 64];

        // ---- stage this warp's fragments ONCE (live only through phase D) ----
        float4 xb0 = *(const float4*)&hnb[bl * 4096 + (kq + 0) * 128 + lane * 4];
        float4 xb1 = *(const float4*)&hnb[bl * 4096 + (kq + 1) * 128 + lane * 4];
        float4 xb2 = *(const float4*)&hnb[bl * 4096 + (kq + 2) * 128 + lane * 4];
        float4 xb3 = *(const float4*)&hnb[bl * 4096 + (kq + 3) * 128 + lane * 4];
        float4 eg  = *(const float4*)&heb[bl * 128 + lane * 4];

        // idle-lane work: pack ego batch-major for phase E (threads 256..511)
        if (tid >= 256) {
            int t = tid - 256, b2 = t >> 7, dd = t & 127;
            ego2[2 * dd + b2] = heb[b2 * 128 + dd];
        }

        // ---- phase B: 4 neighbor dots + redundant ego dot, one shfl tree ----
        {
            float4 vN = *(const float4*)&vs[D + lane * 4];
            float4 vE = *(const float4*)&vs[lane * 4];
            float p0 = xb0.x * vN.x + xb0.y * vN.y + xb0.z * vN.z + xb0.w * vN.w;
            float p1 = xb1.x * vN.x + xb1.y * vN.y + xb1.z * vN.z + xb1.w * vN.w;
            float p2 = xb2.x * vN.x + xb2.y * vN.y + xb2.z * vN.z + xb2.w * vN.w;
            float p3 = xb3.x * vN.x + xb3.y * vN.y + xb3.z * vN.z + xb3.w * vN.w;
            float pe = eg.x  * vE.x + eg.y  * vE.y + eg.z  * vE.z + eg.w  * vE.w;
            #pragma unroll
            for (int o = 16; o > 0; o >>= 1) {
                p0 += __shfl_xor_sync(0xffffffffu, p0, o);
                p1 += __shfl_xor_sync(0xffffffffu, p1, o);
                p2 += __shfl_xor_sync(0xffffffffu, p2, o);
                p3 += __shfl_xor_sync(0xffffffffu, p3, o);
                pe += __shfl_xor_sync(0xffffffffu, pe, o);
            }
            if (lane < 4) {
                float myv = (lane == 0) ? p0 : (lane == 1) ? p1 : (lane == 2) ? p2 : p3;
                float lg = myv + pe;
                lg = (lg > 0.f) ? lg : 0.2f * lg;              // leaky_relu(0.2)
                logit[m0 + lane] = (mskb[m0 + lane] > 0) ? lg : NEG_INF;
            }
        }
        __syncthreads();   // B2

        // ---- phase C: masked softmax over K (warps 0,1) ----
        if (warp < 2) {
            float x = logit[warp * KNBR + lane];
            float mx = x;
            #pragma unroll
            for (int o = 16; o > 0; o >>= 1) mx = fmaxf(mx, __shfl_xor_sync(0xffffffffu, mx, o));
            float ee = (x == NEG_INF) ? 0.f : __expf(x - mx);
            float ss = ee;
            #pragma unroll
            for (int o = 16; o > 0; o >>= 1) ss += __shfl_xor_sync(0xffffffffu, ss, o);
            attn[warp * KNBR + lane] = (ss > 0.f) ? (ee / ss) : 0.f;
        }
        __syncthreads();   // B3

        // ---- phase D: weighted partials from the staged registers ----
        {
            float a0 = attn[m0 + 0];
            float a1 = attn[m0 + 1];
            float a2 = attn[m0 + 2];
            float a3 = attn[m0 + 3];
            float4 acc;
            acc.x = fmaf(a3, xb3.x, fmaf(a2, xb2.x, fmaf(a1, xb1.x, a0 * xb0.x)));
            acc.y = fmaf(a3, xb3.y, fmaf(a2, xb2.y, fmaf(a1, xb1.y, a0 * xb0.y)));
            acc.z = fmaf(a3, xb3.z, fmaf(a2, xb2.z, fmaf(a1, xb1.z, a0 * xb0.z)));
            acc.w = fmaf(a3, xb3.w, fmaf(a2, xb2.w, fmaf(a1, xb1.w, a0 * xb0.w)));
            ((float4*)red)[warp * 32 + lane] = acc;
        }
        __syncthreads();   // B4

        // ---- cross-warp reduce (8 partials per (row,dim)) ----
        if (tid < 256) {
            int bl2 = tid >> 7, dd = tid & 127;
            const float* rb = &red[bl2 * 1024 + dd];
            float a = rb[0] + rb[128] + rb[256] + rb[384] +
                      rb[512] + rb[640] + rb[768] + rb[896];
            agg2[2 * dd + bl2] = a;
        }
        __syncthreads();   // B5

        // ---- phase E: out = tanh([agg|ego] @ [Wmsg|Wself]^T + b), FFMA2 ----
        {
            const unsigned long long* xq =
                (const unsigned long long*)((g < 2) ? agg2 : ego2);
            unsigned long long acc = 0ull;
            #pragma unroll
            for (int j = 0; j < 64; j += 2) {
                ulonglong2 xx = *(const ulonglong2*)&xq[d0 + j];
                unsigned long long w0, w1;
                unsigned int wa = __float_as_uint(wreg[j]);
                unsigned int wb = __float_as_uint(wreg[j + 1]);
                asm("mov.b64 %0, {%1,%1};" : "=l"(w0) : "r"(wa));
                asm("mov.b64 %0, {%1,%1};" : "=l"(w1) : "r"(wb));
                asm("fma.rn.f32x2 %0, %1, %2, %3;" : "=l"(acc) : "l"(w0), "l"(xx.x), "l"(acc));
                asm("fma.rn.f32x2 %0, %1, %2, %3;" : "=l"(acc) : "l"(w1), "l"(xx.y), "l"(acc));
            }
            ((unsigned long long*)red)[g * 128 + e] = acc;
        }
        __syncthreads();   // B6

        if (tid < D) {
            const float2* r = (const float2*)red;
            float2 r0 = r[0 * 128 + tid];
            float2 r1 = r[1 * 128 + tid];
            float2 r2 = r[2 * 128 + tid];
            float2 r3 = r[3 * 128 + tid];
            float o0 = tanhf(r0.x + r1.x + r2.x + r3.x + bb);
            float o1 = tanhf(r0.y + r1.y + r2.y + r3.y + bb);
            size_t row = (size_t)(2 * p) * D;
            out[row + tid]     = o0;
            out[row + D + tid] = o1;
        }
    }
    cp_waitall();
}

// ---------------- launch ----------------
extern "C" void kernel_launch(void* const* d_in, const int* in_sizes, int n_in,
                              void* d_out, int out_size) {
    const float* h_ego  = (const float*)d_in[0];
    const float* h_nei  = (const float*)d_in[1];
    const int*   nmask  = (const int*)  d_in[2];
    const float* Wmsg   = (const float*)d_in[3];
    const float* Wattn  = (const float*)d_in[4];
    const float* Wself  = (const float*)d_in[5];
    const float* bself  = (const float*)d_in[6];
    float* out = (float*)d_out;

    int sms = 0;
    cudaDeviceGetAttribute(&sms, cudaDevAttrMultiProcessorCount, 0);
    if (sms <= 0) sms = 148;

    cudaFuncSetAttribute(gat_kernel, cudaFuncAttributeMaxDynamicSharedMemorySize, SMEM_BYTES);

    prep_kernel<<<1, D>>>(Wmsg, Wattn);
    gat_kernel<<<sms, T, SMEM_BYTES>>>(h_ego, h_nei, nmask, Wmsg, Wself, bself, out);
}

// round 4
// speedup vs baseline: 1.2074x; 1.0632x over previous
#include <cuda_runtime.h>
#include <cstdint>
#include <math.h>

#define KNBR  32
#define D     128
#define T     512
#define B_TOT 32768
#define NPAIR (B_TOT / 2)

// smem layout (float offsets)
#define OFF_HN    0        // 2 * 8192 double-buffered h_nei (2 rows/iter)
#define OFF_HE    16384    // 2 * 256
#define OFF_MSK   16896    // 2 * 64 ints
#define OFF_VS    17024    // 256 (v_ego | v_nbr)
#define OFF_EGO2  17280    // 256 batch-packed ego
#define OFF_AGG2  17536    // 256 batch-packed agg
#define OFF_REDD  17792    // 1024: phase-D partials (8 warps x 128)
#define OFF_REDE  18816    // 1024: phase-E accumulators (4 x 128 float2)
#define OFF_LOG   19840    // 64
#define OFF_ATT   19904    // 64
#define SMEM_FLOATS 19968
#define SMEM_BYTES (SMEM_FLOATS * 4)

#define BAR_A() asm volatile("bar.sync 1, 256;" ::: "memory")
#define BAR_B() asm volatile("bar.sync 2, 256;" ::: "memory")

__device__ float g_v[2 * D];   // [0:128) v_ego = W_msg^T a_ego, [128:256) v_nbr

// ---------------- prologue: v = W_msg^T @ a ----------------
__global__ void prep_kernel(const float* __restrict__ Wmsg,
                            const float* __restrict__ Wattn) {
    int d = threadIdx.x;   // 128 threads
    float ve = 0.f, vn = 0.f;
    #pragma unroll 8
    for (int e = 0; e < D; e++) {
        float w = Wmsg[e * D + d];
        ve = fmaf(Wattn[e], w, ve);
        vn = fmaf(Wattn[D + e], w, vn);
    }
    g_v[d] = ve;
    g_v[D + d] = vn;
}

// ---------------- cp.async helpers ----------------
__device__ __forceinline__ void cp16(uint32_t dst, const void* src) {
    asm volatile("cp.async.cg.shared.global [%0], [%1], 16;" :: "r"(dst), "l"(src));
}
__device__ __forceinline__ void cp_commit() { asm volatile("cp.async.commit_group;"); }
__device__ __forceinline__ void cp_wait1()  { asm volatile("cp.async.wait_group 1;" ::: "memory"); }
__device__ __forceinline__ void cp_waitall(){ asm volatile("cp.async.wait_all;" ::: "memory"); }

__device__ __forceinline__ void prefetch_pair(int p, int buf, int tid, uint32_t smem_u32,
                                              const float* __restrict__ h_nei,
                                              const float* __restrict__ h_ego,
                                              const int*   __restrict__ nbr_mask) {
    const float* src = h_nei + (size_t)p * 8192;
    uint32_t hdst = smem_u32 + (uint32_t)(OFF_HN + buf * 8192) * 4u;
    #pragma unroll
    for (int i = 0; i < 4; i++) {
        int idx = tid + i * T;
        cp16(hdst + (uint32_t)idx * 16u, src + idx * 4);
    }
    if (tid < 64)
        cp16(smem_u32 + (uint32_t)(OFF_HE + buf * 256 + tid * 4) * 4u,
             h_ego + (size_t)p * 256 + tid * 4);
    if (tid < 16)
        cp16(smem_u32 + (uint32_t)(OFF_MSK + buf * 64 + tid * 4) * 4u,
             nbr_mask + (size_t)p * 64 + tid * 4);
}

// ---------------- FFMA2 projection: 1 output dim x 64 inputs, 2 rows packed ----------------
__device__ __forceinline__ void proj64(const unsigned long long* __restrict__ xq,
                                       const float* __restrict__ wreg,
                                       int d0, unsigned long long* dst) {
    unsigned long long acc = 0ull;
    #pragma unroll
    for (int j = 0; j < 64; j += 2) {
        ulonglong2 xx = *(const ulonglong2*)&xq[d0 + j];
        unsigned long long w0, w1;
        unsigned int wa = __float_as_uint(wreg[j]);
        unsigned int wb = __float_as_uint(wreg[j + 1]);
        asm("mov.b64 %0, {%1,%1};" : "=l"(w0) : "r"(wa));
        asm("mov.b64 %0, {%1,%1};" : "=l"(w1) : "r"(wb));
        asm("fma.rn.f32x2 %0, %1, %2, %3;" : "=l"(acc) : "l"(w0), "l"(xx.x), "l"(acc));
        asm("fma.rn.f32x2 %0, %1, %2, %3;" : "=l"(acc) : "l"(w1), "l"(xx.y), "l"(acc));
    }
    *dst = acc;
}

// ---------------- main fused kernel ----------------
__global__ void __launch_bounds__(T, 1)
gat_kernel(const float* __restrict__ h_ego, const float* __restrict__ h_nei,
           const int*   __restrict__ nbr_mask,
           const float* __restrict__ Wmsg, const float* __restrict__ Wself,
           const float* __restrict__ bself, float* __restrict__ out) {
    extern __shared__ float sm[];
    float* hn    = sm + OFF_HN;
    float* he    = sm + OFF_HE;
    int*   msk   = (int*)(sm + OFF_MSK);
    float* vs    = sm + OFF_VS;
    float* ego2  = sm + OFF_EGO2;
    float* agg2  = sm + OFF_AGG2;
    float* redD  = sm + OFF_REDD;
    float* redE  = sm + OFF_REDE;
    float* logit = sm + OFF_LOG;
    float* attn  = sm + OFF_ATT;

    const int tid  = threadIdx.x;
    const int lane = tid & 31;
    const int warp = tid >> 5;
    const int g    = tid >> 7;            // 0..3
    const int e    = tid & 127;
    const int d0   = (g & 1) * 64;
    const bool isA = (tid < 256);

    // group A (g 0,1): W_msg slice;  group B (g 2,3): W_self slice
    const float* Wsrc = isA ? Wmsg : Wself;
    float wreg[64];
    #pragma unroll
    for (int j = 0; j < 64; j += 4) {
        float4 t4 = *(const float4*)&Wsrc[e * D + d0 + j];
        wreg[j] = t4.x; wreg[j + 1] = t4.y; wreg[j + 2] = t4.z; wreg[j + 3] = t4.w;
    }
    if (tid < 2 * D) vs[tid] = g_v[tid];
    float bb = (tid < D) ? __ldg(bself + tid) : 0.f;
    __syncthreads();

    const uint32_t smem_u32 = (uint32_t)__cvta_generic_to_shared(sm);
    const float NEG_INF = __int_as_float(0xff800000);
    const int G = gridDim.x;

    // group A geometry: 8 warps, warps 0-3 -> row 0, warps 4-7 -> row 1; 8 k's each
    const int rowA = warp >> 2;
    const int kq   = (warp & 3) * 8;

    int p = blockIdx.x;
    int s = 0;
    if (p < NPAIR) prefetch_pair(p, 0, tid, smem_u32, h_nei, h_ego, nbr_mask);
    cp_commit();

    for (; p < NPAIR; p += G, s ^= 1) {
        int pn = p + G;
        if (pn < NPAIR) prefetch_pair(pn, s ^ 1, tid, smem_u32, h_nei, h_ego, nbr_mask);
        cp_commit();
        cp_wait1();
        __syncthreads();   // B0: buffer s ready

        const float* hnb  = &hn[s * 8192];
        const float* heb  = &he[s * 256];
        const int*   mskb = &msk[s * 64];

        if (isA) {
            // ======== GROUP A: attention chain + msg projection ========
            const float* hb = &hnb[rowA * 4096 + kq * 128];
            {
                // 8 raw neighbor dots
                float4 vN = *(const float4*)&vs[D + lane * 4];
                float a0, a1, a2, a3, a4, a5, a6, a7;
                {
                    float4 x;
                    x = *(const float4*)&hb[0 * 128 + lane * 4];
                    a0 = x.x * vN.x + x.y * vN.y + x.z * vN.z + x.w * vN.w;
                    x = *(const float4*)&hb[1 * 128 + lane * 4];
                    a1 = x.x * vN.x + x.y * vN.y + x.z * vN.z + x.w * vN.w;
                    x = *(const float4*)&hb[2 * 128 + lane * 4];
                    a2 = x.x * vN.x + x.y * vN.y + x.z * vN.z + x.w * vN.w;
                    x = *(const float4*)&hb[3 * 128 + lane * 4];
                    a3 = x.x * vN.x + x.y * vN.y + x.z * vN.z + x.w * vN.w;
                    x = *(const float4*)&hb[4 * 128 + lane * 4];
                    a4 = x.x * vN.x + x.y * vN.y + x.z * vN.z + x.w * vN.w;
                    x = *(const float4*)&hb[5 * 128 + lane * 4];
                    a5 = x.x * vN.x + x.y * vN.y + x.z * vN.z + x.w * vN.w;
                    x = *(const float4*)&hb[6 * 128 + lane * 4];
                    a6 = x.x * vN.x + x.y * vN.y + x.z * vN.z + x.w * vN.w;
                    x = *(const float4*)&hb[7 * 128 + lane * 4];
                    a7 = x.x * vN.x + x.y * vN.y + x.z * vN.z + x.w * vN.w;
                }
                #pragma unroll
                for (int o = 16; o > 0; o >>= 1) {
                    a0 += __shfl_xor_sync(0xffffffffu, a0, o);
                    a1 += __shfl_xor_sync(0xffffffffu, a1, o);
                    a2 += __shfl_xor_sync(0xffffffffu, a2, o);
                    a3 += __shfl_xor_sync(0xffffffffu, a3, o);
                    a4 += __shfl_xor_sync(0xffffffffu, a4, o);
                    a5 += __shfl_xor_sync(0xffffffffu, a5, o);
                    a6 += __shfl_xor_sync(0xffffffffu, a6, o);
                    a7 += __shfl_xor_sync(0xffffffffu, a7, o);
                }
                if (lane == 0) {
                    float* lg = &logit[rowA * KNBR + kq];
                    lg[0] = a0; lg[1] = a1; lg[2] = a2; lg[3] = a3;
                    lg[4] = a4; lg[5] = a5; lg[6] = a6; lg[7] = a7;
                }
            }
            BAR_A();   // A1

            // softmax warps (0 -> row 0, 4 -> row 1)
            if ((warp & 3) == 0) {
                float4 vE = *(const float4*)&vs[lane * 4];
                float4 eg = *(const float4*)&heb[rowA * 128 + lane * 4];
                float pe = eg.x * vE.x + eg.y * vE.y + eg.z * vE.z + eg.w * vE.w;
                #pragma unroll
                for (int o = 16; o > 0; o >>= 1) pe += __shfl_xor_sync(0xffffffffu, pe, o);
                float x = logit[rowA * KNBR + lane] + pe;
                x = (x > 0.f) ? x : 0.2f * x;                         // leaky_relu
                x = (mskb[rowA * KNBR + lane] > 0) ? x : NEG_INF;     // mask
                float mx = x;
                #pragma unroll
                for (int o = 16; o > 0; o >>= 1) mx = fmaxf(mx, __shfl_xor_sync(0xffffffffu, mx, o));
                float ee = (x == NEG_INF) ? 0.f : __expf(x - mx);
                float ss = ee;
                #pragma unroll
                for (int o = 16; o > 0; o >>= 1) ss += __shfl_xor_sync(0xffffffffu, ss, o);
                attn[rowA * KNBR + lane] = (ss > 0.f) ? (ee / ss) : 0.f;
            }
            BAR_A();   // A2

            // phase D: attn-weighted partial aggregation (re-read fragments)
            {
                const float* at = &attn[rowA * KNBR + kq];
                float4 acc = {0.f, 0.f, 0.f, 0.f};
                #pragma unroll
                for (int i = 0; i < 8; i++) {
                    float ak = at[i];
                    float4 x = *(const float4*)&hb[i * 128 + lane * 4];
                    acc.x = fmaf(ak, x.x, acc.x);
                    acc.y = fmaf(ak, x.y, acc.y);
                    acc.z = fmaf(ak, x.z, acc.z);
                    acc.w = fmaf(ak, x.w, acc.w);
                }
                ((float4*)redD)[warp * 32 + lane] = acc;
            }
            BAR_A();   // A3

            // reduce 4 partials per (row,dim) -> batch-packed agg2
            {
                int r  = tid >> 7;        // 0..1
                int dd = tid & 127;
                const float* rb = &redD[(4 * r) * 128 + dd];
                agg2[2 * dd + r] = rb[0] + rb[128] + rb[256] + rb[384];
            }
            BAR_A();   // A4

            // msg projection
            proj64((const unsigned long long*)agg2, wreg, d0,
                   &((unsigned long long*)redE)[g * 128 + e]);
        } else {
            // ======== GROUP B: ego pack + self projection (independent) ========
            {
                int t = tid - 256, r = t >> 7, dd = t & 127;
                ego2[2 * dd + r] = heb[r * 128 + dd];
            }
            BAR_B();   // B1
            proj64((const unsigned long long*)ego2, wreg, d0,
                   &((unsigned long long*)redE)[g * 128 + e]);
        }

        __syncthreads();   // B_comb: redE (all 4 groups) ready

        if (tid < D) {
            const float2* r = (const float2*)redE;
            float2 r0 = r[0 * 128 + tid];
            float2 r1 = r[1 * 128 + tid];
            float2 r2 = r[2 * 128 + tid];
            float2 r3 = r[3 * 128 + tid];
            float o0 = tanhf(r0.x + r1.x + r2.x + r3.x + bb);
            float o1 = tanhf(r0.y + r1.y + r2.y + r3.y + bb);
            size_t row = (size_t)(2 * p) * D;
            out[row + tid]     = o0;
            out[row + D + tid] = o1;
        }
    }
    cp_waitall();
}

// ---------------- launch ----------------
extern "C" void kernel_launch(void* const* d_in, const int* in_sizes, int n_in,
                              void* d_out, int out_size) {
    const float* h_ego  = (const float*)d_in[0];
    const float* h_nei  = (const float*)d_in[1];
    const int*   nmask  = (const int*)  d_in[2];
    const float* Wmsg   = (const float*)d_in[3];
    const float* Wattn  = (const float*)d_in[4];
    const float* Wself  = (const float*)d_in[5];
    const float* bself  = (const float*)d_in[6];
    float* out = (float*)d_out;

    int sms = 0;
    cudaDeviceGetAttribute(&sms, cudaDevAttrMultiProcessorCount, 0);
    if (sms <= 0) sms = 148;

    cudaFuncSetAttribute(gat_kernel, cudaFuncAttributeMaxDynamicSharedMemorySize, SMEM_BYTES);

    prep_kernel<<<1, D>>>(Wmsg, Wattn);
    gat_kernel<<<sms, T, SMEM_BYTES>>>(h_ego, h_nei, nmask, Wmsg, Wself, bself, out);
}

// round 5
// speedup vs baseline: 1.4239x; 1.1793x over previous
#include <cuda_runtime.h>
#include <cstdint>
#include <math.h>

#define KNBR  32
#define D     128
#define T     512
#define B_TOT 32768
#define NQUAD (B_TOT / 4)   // 4 rows (2 pairs) per macro-iteration

// smem layout (float offsets)
#define OFF_HN    0        // 2 * 16384 double-buffered (4 rows x 4096)
#define OFF_HE    32768    // 2 * 512
#define OFF_MSK   33792    // 2 * 128 ints
#define OFF_VS    34048    // 256 (v_ego | v_nbr)
#define OFF_EGO2  34304    // 512: ego2[pair*256 + 2*d + r]
#define OFF_AGG2  34816    // 512: agg2[pair*256 + 2*d + r]
#define OFF_REDD  35328    // 2048: 16 warps x 128
#define OFF_REDE  37376    // 2048: 2 pairs x 4 groups x 128 (float2)
#define OFF_LOG   39424    // 128
#define OFF_ATT   39552    // 128
#define SMEM_FLOATS 39680
#define SMEM_BYTES (SMEM_FLOATS * 4)

__device__ float g_v[2 * D];   // [0:128) v_ego = W_msg^T a_ego, [128:256) v_nbr

// ---------------- prologue: v = W_msg^T @ a ----------------
__global__ void prep_kernel(const float* __restrict__ Wmsg,
                            const float* __restrict__ Wattn) {
    int d = threadIdx.x;   // 128 threads
    float ve = 0.f, vn = 0.f;
    #pragma unroll 8
    for (int e = 0; e < D; e++) {
        float w = Wmsg[e * D + d];
        ve = fmaf(Wattn[e], w, ve);
        vn = fmaf(Wattn[D + e], w, vn);
    }
    g_v[d] = ve;
    g_v[D + d] = vn;
}

// ---------------- cp.async helpers ----------------
__device__ __forceinline__ void cp16(uint32_t dst, const void* src) {
    asm volatile("cp.async.cg.shared.global [%0], [%1], 16;" :: "r"(dst), "l"(src));
}
__device__ __forceinline__ void cp_commit() { asm volatile("cp.async.commit_group;"); }
__device__ __forceinline__ void cp_wait1()  { asm volatile("cp.async.wait_group 1;" ::: "memory"); }
__device__ __forceinline__ void cp_waitall(){ asm volatile("cp.async.wait_all;" ::: "memory"); }

__device__ __forceinline__ void prefetch_quad(int q, int buf, int tid, uint32_t smem_u32,
                                              const float* __restrict__ h_nei,
                                              const float* __restrict__ h_ego,
                                              const int*   __restrict__ nbr_mask) {
    const float* src = h_nei + (size_t)q * 16384;
    uint32_t hdst = smem_u32 + (uint32_t)(OFF_HN + buf * 16384) * 4u;
    #pragma unroll
    for (int i = 0; i < 8; i++) {                        // 4096 float4
        int idx = tid + i * T;
        cp16(hdst + (uint32_t)idx * 16u, src + idx * 4);
    }
    if (tid < 128)
        cp16(smem_u32 + (uint32_t)(OFF_HE + buf * 512 + tid * 4) * 4u,
             h_ego + (size_t)q * 512 + tid * 4);
    if (tid < 32)
        cp16(smem_u32 + (uint32_t)(OFF_MSK + buf * 128 + tid * 4) * 4u,
             nbr_mask + (size_t)q * 128 + tid * 4);
}

// ---------------- FFMA2 projection: 1 out dim x 64 inputs, 2 rows packed ----------------
__device__ __forceinline__ void proj64(const unsigned long long* __restrict__ xq,
                                       const float* __restrict__ wreg,
                                       int d0, unsigned long long* dst) {
    unsigned long long acc = 0ull;
    #pragma unroll
    for (int j = 0; j < 64; j += 2) {
        ulonglong2 xx = *(const ulonglong2*)&xq[d0 + j];
        unsigned long long w0, w1;
        unsigned int wa = __float_as_uint(wreg[j]);
        unsigned int wb = __float_as_uint(wreg[j + 1]);
        asm("mov.b64 %0, {%1,%1};" : "=l"(w0) : "r"(wa));
        asm("mov.b64 %0, {%1,%1};" : "=l"(w1) : "r"(wb));
        asm("fma.rn.f32x2 %0, %1, %2, %3;" : "=l"(acc) : "l"(w0), "l"(xx.x), "l"(acc));
        asm("fma.rn.f32x2 %0, %1, %2, %3;" : "=l"(acc) : "l"(w1), "l"(xx.y), "l"(acc));
    }
    *dst = acc;
}

// ---------------- main fused kernel ----------------
__global__ void __launch_bounds__(T, 1)
gat_kernel(const float* __restrict__ h_ego, const float* __restrict__ h_nei,
           const int*   __restrict__ nbr_mask,
           const float* __restrict__ Wmsg, const float* __restrict__ Wself,
           const float* __restrict__ bself, float* __restrict__ out) {
    extern __shared__ float sm[];
    float* hn    = sm + OFF_HN;
    float* he    = sm + OFF_HE;
    int*   msk   = (int*)(sm + OFF_MSK);
    float* vs    = sm + OFF_VS;
    float* ego2  = sm + OFF_EGO2;
    float* agg2  = sm + OFF_AGG2;
    float* redD  = sm + OFF_REDD;
    float* redE  = sm + OFF_REDE;
    float* logit = sm + OFF_LOG;
    float* attn  = sm + OFF_ATT;

    const int tid  = threadIdx.x;
    const int lane = tid & 31;
    const int warp = tid >> 5;
    const int g    = tid >> 7;            // 0..3: {Wmsg-lo, Wmsg-hi, Wself-lo, Wself-hi}
    const int e    = tid & 127;
    const int d0   = (g & 1) * 64;
    const int rr   = warp >> 2;           // row within quad (0..3) for dots/aggregation
    const int kq   = (warp & 3) * 8;      // 8 k's per warp

    // W slice in registers
    const float* Wsrc = (g < 2) ? Wmsg : Wself;
    float wreg[64];
    #pragma unroll
    for (int j = 0; j < 64; j += 4) {
        float4 t4 = *(const float4*)&Wsrc[e * D + d0 + j];
        wreg[j] = t4.x; wreg[j + 1] = t4.y; wreg[j + 2] = t4.z; wreg[j + 3] = t4.w;
    }
    if (tid < 2 * D) vs[tid] = g_v[tid];
    float bb = __ldg(bself + (tid & 127));
    __syncthreads();

    const uint32_t smem_u32 = (uint32_t)__cvta_generic_to_shared(sm);
    const float NEG_INF = __int_as_float(0xff800000);
    const int G = gridDim.x;

    int q = blockIdx.x;
    int s = 0;
    if (q < NQUAD) prefetch_quad(q, 0, tid, smem_u32, h_nei, h_ego, nbr_mask);
    cp_commit();

    for (; q < NQUAD; q += G, s ^= 1) {
        int qn = q + G;
        if (qn < NQUAD) prefetch_quad(qn, s ^ 1, tid, smem_u32, h_nei, h_ego, nbr_mask);
        cp_commit();
        cp_wait1();
        __syncthreads();   // B0: buffer s ready

        const float* hnb  = &hn[s * 16384];
        const float* heb  = &he[s * 512];
        const int*   mskb = &msk[s * 128];
        const float* hb   = &hnb[rr * 4096 + kq * 128];

        // ---- dots: 8 raw neighbor logits per warp ----
        {
            float4 vN = *(const float4*)&vs[D + lane * 4];
            float a[8];
            #pragma unroll
            for (int i = 0; i < 8; i++) {
                float4 x = *(const float4*)&hb[i * 128 + lane * 4];
                a[i] = x.x * vN.x + x.y * vN.y + x.z * vN.z + x.w * vN.w;
            }
            #pragma unroll
            for (int o = 16; o > 0; o >>= 1) {
                #pragma unroll
                for (int i = 0; i < 8; i++)
                    a[i] += __shfl_xor_sync(0xffffffffu, a[i], o);
            }
            if (lane == 0) {
                float* lg = &logit[rr * KNBR + kq];
                #pragma unroll
                for (int i = 0; i < 8; i++) lg[i] = a[i];
            }
        }
        // pack ego batch-major while dots are in flight elsewhere
        {
            int dd = tid & 127;
            ego2[(rr >> 1) * 256 + 2 * dd + (rr & 1)] = heb[rr * 128 + dd];
        }
        __syncthreads();   // A1

        // ---- softmax: warps 0..3, one row each ----
        if (warp < 4) {
            float4 vE = *(const float4*)&vs[lane * 4];
            float4 eg = *(const float4*)&heb[warp * 128 + lane * 4];
            float pe = eg.x * vE.x + eg.y * vE.y + eg.z * vE.z + eg.w * vE.w;
            #pragma unroll
            for (int o = 16; o > 0; o >>= 1) pe += __shfl_xor_sync(0xffffffffu, pe, o);
            float x = logit[warp * KNBR + lane] + pe;
            x = (x > 0.f) ? x : 0.2f * x;                          // leaky_relu
            x = (mskb[warp * KNBR + lane] > 0) ? x : NEG_INF;      // mask
            float mx = x;
            #pragma unroll
            for (int o = 16; o > 0; o >>= 1) mx = fmaxf(mx, __shfl_xor_sync(0xffffffffu, mx, o));
            float ee = (x == NEG_INF) ? 0.f : __expf(x - mx);
            float ss = ee;
            #pragma unroll
            for (int o = 16; o > 0; o >>= 1) ss += __shfl_xor_sync(0xffffffffu, ss, o);
            attn[warp * KNBR + lane] = (ss > 0.f) ? (ee / ss) : 0.f;
        }
        __syncthreads();   // A2

        // ---- weighted partial aggregation (re-read fragments) ----
        {
            const float* at = &attn[rr * KNBR + kq];
            float4 acc = {0.f, 0.f, 0.f, 0.f};
            #pragma unroll
            for (int i = 0; i < 8; i++) {
                float ak = at[i];
                float4 x = *(const float4*)&hb[i * 128 + lane * 4];
                acc.x = fmaf(ak, x.x, acc.x);
                acc.y = fmaf(ak, x.y, acc.y);
                acc.z = fmaf(ak, x.z, acc.z);
                acc.w = fmaf(ak, x.w, acc.w);
            }
            ((float4*)redD)[warp * 32 + lane] = acc;
        }
        __syncthreads();   // A3

        // ---- reduce 4 partials per (row,dim) -> batch-packed agg2 ----
        {
            int r  = tid >> 7;        // 0..3 (row)
            int dd = tid & 127;
            const float* rb = &redD[(4 * r) * 128 + dd];
            agg2[(r >> 1) * 256 + 2 * dd + (r & 1)] =
                rb[0] + rb[128] + rb[256] + rb[384];
        }
        __syncthreads();   // A4

        // ---- projection: both pairs, FFMA2 ----
        {
            const unsigned long long* xbase =
                (const unsigned long long*)((g < 2) ? agg2 : ego2);
            unsigned long long* rE = (unsigned long long*)redE;
            proj64(xbase,       wreg, d0, &rE[0 * 512 + g * 128 + e]);
            proj64(xbase + 128, wreg, d0, &rE[1 * 512 + g * 128 + e]);
        }
        __syncthreads();   // A5

        // ---- combine + tanh + store (256 threads: pair x dim) ----
        if (tid < 256) {
            int pr = tid >> 7, dd = tid & 127;
            const float2* r = (const float2*)redE + pr * 512;
            float2 r0 = r[0 * 128 + dd];
            float2 r1 = r[1 * 128 + dd];
            float2 r2 = r[2 * 128 + dd];
            float2 r3 = r[3 * 128 + dd];
            float o0 = tanhf(r0.x + r1.x + r2.x + r3.x + bb);
            float o1 = tanhf(r0.y + r1.y + r2.y + r3.y + bb);
            size_t row = ((size_t)4 * q + 2 * pr) * D;
            out[row + dd]     = o0;
            out[row + D + dd] = o1;
        }
    }
    cp_waitall();
}

// ---------------- launch ----------------
extern "C" void kernel_launch(void* const* d_in, const int* in_sizes, int n_in,
                              void* d_out, int out_size) {
    const float* h_ego  = (const float*)d_in[0];
    const float* h_nei  = (const float*)d_in[1];
    const int*   nmask  = (const int*)  d_in[2];
    const float* Wmsg   = (const float*)d_in[3];
    const float* Wattn  = (const float*)d_in[4];
    const float* Wself  = (const float*)d_in[5];
    const float* bself  = (const float*)d_in[6];
    float* out = (float*)d_out;

    int sms = 0;
    cudaDeviceGetAttribute(&sms, cudaDevAttrMultiProcessorCount, 0);
    if (sms <= 0) sms = 148;

    cudaFuncSetAttribute(gat_kernel, cudaFuncAttributeMaxDynamicSharedMemorySize, SMEM_BYTES);

    prep_kernel<<<1, D>>>(Wmsg, Wattn);
    gat_kernel<<<sms, T, SMEM_BYTES>>>(h_ego, h_nei, nmask, Wmsg, Wself, bself, out);
}

// round 6
// speedup vs baseline: 1.6231x; 1.1399x over previous
#include <cuda_runtime.h>
#include <cstdint>
#include <math.h>

#define KNBR  32
#define D     128
#define T     512
#define B_TOT 32768
#define NQUAD (B_TOT / 4)   // 4 rows (2 pairs) per macro-iteration

// smem layout (float offsets)
#define OFF_HN    0        // 2 * 16384 double-buffered (4 rows x 4096)
#define OFF_HE    32768    // 2 * 512
#define OFF_MSK   33792    // 2 * 128 ints
#define OFF_VS    34048    // 256 (v_ego | v_nbr)
#define OFF_EGO2  34304    // 512: ego2[pair*256 + 2*d + r]
#define OFF_AGG2  34816    // 512: agg2[pair*256 + 2*d + r]
#define OFF_REDD  35328    // 2048: 16 warps x 128
#define OFF_REDE  37376    // 2048: 2 pairs x 4 groups x 128 (float2)
#define OFF_LOG   39424    // 128
#define OFF_ATT   39552    // 128
#define SMEM_FLOATS 39680
#define SMEM_BYTES (SMEM_FLOATS * 4)

__device__ float g_v[2 * D];   // [0:128) v_ego = W_msg^T a_ego, [128:256) v_nbr

// ---------------- prologue: v = W_msg^T @ a ----------------
__global__ void prep_kernel(const float* __restrict__ Wmsg,
                            const float* __restrict__ Wattn) {
    int d = threadIdx.x;   // 128 threads
    float ve = 0.f, vn = 0.f;
    #pragma unroll 8
    for (int e = 0; e < D; e++) {
        float w = Wmsg[e * D + d];
        ve = fmaf(Wattn[e], w, ve);
        vn = fmaf(Wattn[D + e], w, vn);
    }
    g_v[d] = ve;
    g_v[D + d] = vn;
}

// ---------------- cp.async helpers ----------------
__device__ __forceinline__ void cp16(uint32_t dst, const void* src) {
    asm volatile("cp.async.cg.shared.global [%0], [%1], 16;" :: "r"(dst), "l"(src));
}
__device__ __forceinline__ void cp_commit() { asm volatile("cp.async.commit_group;"); }
__device__ __forceinline__ void cp_wait1()  { asm volatile("cp.async.wait_group 1;" ::: "memory"); }
__device__ __forceinline__ void cp_waitall(){ asm volatile("cp.async.wait_all;" ::: "memory"); }

__device__ __forceinline__ void prefetch_quad(int q, int buf, int tid, uint32_t smem_u32,
                                              const float* __restrict__ h_nei,
                                              const float* __restrict__ h_ego,
                                              const int*   __restrict__ nbr_mask) {
    const float* src = h_nei + (size_t)q * 16384;
    uint32_t hdst = smem_u32 + (uint32_t)(OFF_HN + buf * 16384) * 4u;
    #pragma unroll
    for (int i = 0; i < 8; i++) {                        // 4096 float4
        int idx = tid + i * T;
        cp16(hdst + (uint32_t)idx * 16u, src + idx * 4);
    }
    if (tid < 128)
        cp16(smem_u32 + (uint32_t)(OFF_HE + buf * 512 + tid * 4) * 4u,
             h_ego + (size_t)q * 512 + tid * 4);
    if (tid < 32)
        cp16(smem_u32 + (uint32_t)(OFF_MSK + buf * 128 + tid * 4) * 4u,
             nbr_mask + (size_t)q * 128 + tid * 4);
}

// ---------------- FFMA2 projection: 1 out dim x 64 inputs, 2 rows packed ----------------
__device__ __forceinline__ void proj64(const unsigned long long* __restrict__ xq,
                                       const float* __restrict__ wreg,
                                       int d0, unsigned long long* dst) {
    unsigned long long acc = 0ull;
    #pragma unroll
    for (int j = 0; j < 64; j += 2) {
        ulonglong2 xx = *(const ulonglong2*)&xq[d0 + j];
        unsigned long long w0, w1;
        unsigned int wa = __float_as_uint(wreg[j]);
        unsigned int wb = __float_as_uint(wreg[j + 1]);
        asm("mov.b64 %0, {%1,%1};" : "=l"(w0) : "r"(wa));
        asm("mov.b64 %0, {%1,%1};" : "=l"(w1) : "r"(wb));
        asm("fma.rn.f32x2 %0, %1, %2, %3;" : "=l"(acc) : "l"(w0), "l"(xx.x), "l"(acc));
        asm("fma.rn.f32x2 %0, %1, %2, %3;" : "=l"(acc) : "l"(w1), "l"(xx.y), "l"(acc));
    }
    *dst = acc;
}

// ---------------- main fused kernel ----------------
__global__ void __launch_bounds__(T, 1)
gat_kernel(const float* __restrict__ h_ego, const float* __restrict__ h_nei,
           const int*   __restrict__ nbr_mask,
           const float* __restrict__ Wmsg, const float* __restrict__ Wself,
           const float* __restrict__ bself, float* __restrict__ out) {
    extern __shared__ float sm[];
    float* hn    = sm + OFF_HN;
    float* he    = sm + OFF_HE;
    int*   msk   = (int*)(sm + OFF_MSK);
    float* vs    = sm + OFF_VS;
    float* ego2  = sm + OFF_EGO2;
    float* agg2  = sm + OFF_AGG2;
    float* redD  = sm + OFF_REDD;
    float* redE  = sm + OFF_REDE;
    float* logit = sm + OFF_LOG;
    float* attn  = sm + OFF_ATT;

    const int tid  = threadIdx.x;
    const int lane = tid & 31;
    const int warp = tid >> 5;
    const int g    = tid >> 7;            // 0..3: {Wmsg-lo, Wmsg-hi, Wself-lo, Wself-hi}
    const int e    = tid & 127;
    const int d0   = (g & 1) * 64;
    const int rr   = warp >> 2;           // row within quad (0..3)
    const int kq   = (warp & 3) * 8;      // 8 k's per warp

    // W slice in registers
    const float* Wsrc = (g < 2) ? Wmsg : Wself;
    float wreg[64];
    #pragma unroll
    for (int j = 0; j < 64; j += 4) {
        float4 t4 = *(const float4*)&Wsrc[e * D + d0 + j];
        wreg[j] = t4.x; wreg[j + 1] = t4.y; wreg[j + 2] = t4.z; wreg[j + 3] = t4.w;
    }
    if (tid < 2 * D) vs[tid] = g_v[tid];
    float bb = __ldg(bself + (tid & 127));
    __syncthreads();

    const uint32_t smem_u32 = (uint32_t)__cvta_generic_to_shared(sm);
    const float NEG_INF = __int_as_float(0xff800000);
    const int G = gridDim.x;

    int q = blockIdx.x;
    int s = 0;
    if (q < NQUAD) prefetch_quad(q, 0, tid, smem_u32, h_nei, h_ego, nbr_mask);
    cp_commit();

    for (; q < NQUAD; q += G, s ^= 1) {
        int qn = q + G;
        if (qn < NQUAD) prefetch_quad(qn, s ^ 1, tid, smem_u32, h_nei, h_ego, nbr_mask);
        cp_commit();
        cp_wait1();
        __syncthreads();   // B0: buffer s ready

        const float* hnb  = &hn[s * 16384];
        const float* heb  = &he[s * 512];
        const int*   mskb = &msk[s * 128];
        const float* hb   = &hnb[rr * 4096 + kq * 128];

        // ---- stage fragments ONCE; compute raw neighbor dots ----
        float4 f0 = *(const float4*)&hb[0 * 128 + lane * 4];
        float4 f1 = *(const float4*)&hb[1 * 128 + lane * 4];
        float4 f2 = *(const float4*)&hb[2 * 128 + lane * 4];
        float4 f3 = *(const float4*)&hb[3 * 128 + lane * 4];
        float4 f4 = *(const float4*)&hb[4 * 128 + lane * 4];
        float4 f5 = *(const float4*)&hb[5 * 128 + lane * 4];
        float4 f6 = *(const float4*)&hb[6 * 128 + lane * 4];
        float4 f7 = *(const float4*)&hb[7 * 128 + lane * 4];
        {
            float4 vN = *(const float4*)&vs[D + lane * 4];
            float a0 = f0.x * vN.x + f0.y * vN.y + f0.z * vN.z + f0.w * vN.w;
            float a1 = f1.x * vN.x + f1.y * vN.y + f1.z * vN.z + f1.w * vN.w;
            float a2 = f2.x * vN.x + f2.y * vN.y + f2.z * vN.z + f2.w * vN.w;
            float a3 = f3.x * vN.x + f3.y * vN.y + f3.z * vN.z + f3.w * vN.w;
            float a4 = f4.x * vN.x + f4.y * vN.y + f4.z * vN.z + f4.w * vN.w;
            float a5 = f5.x * vN.x + f5.y * vN.y + f5.z * vN.z + f5.w * vN.w;
            float a6 = f6.x * vN.x + f6.y * vN.y + f6.z * vN.z + f6.w * vN.w;
            float a7 = f7.x * vN.x + f7.y * vN.y + f7.z * vN.z + f7.w * vN.w;
            #pragma unroll
            for (int o = 16; o > 0; o >>= 1) {
                a0 += __shfl_xor_sync(0xffffffffu, a0, o);
                a1 += __shfl_xor_sync(0xffffffffu, a1, o);
                a2 += __shfl_xor_sync(0xffffffffu, a2, o);
                a3 += __shfl_xor_sync(0xffffffffu, a3, o);
                a4 += __shfl_xor_sync(0xffffffffu, a4, o);
                a5 += __shfl_xor_sync(0xffffffffu, a5, o);
                a6 += __shfl_xor_sync(0xffffffffu, a6, o);
                a7 += __shfl_xor_sync(0xffffffffu, a7, o);
            }
            if (lane == 0) {
                float* lg = &logit[rr * KNBR + kq];
                lg[0] = a0; lg[1] = a1; lg[2] = a2; lg[3] = a3;
                lg[4] = a4; lg[5] = a5; lg[6] = a6; lg[7] = a7;
            }
        }
        // pack ego batch-major (threads 256..511 handle 2 each) — needed before A1
        if (tid >= 256) {
            int t = tid - 256;
            #pragma unroll
            for (int i = 0; i < 2; i++) {
                int idx = t + i * 256;          // 0..511
                int r = idx >> 7, dd = idx & 127;
                ego2[(r >> 1) * 256 + 2 * dd + (r & 1)] = heb[r * 128 + dd];
            }
        }
        __syncthreads();   // A1: logits + ego2 ready

        // ---- softmax (warps 0..3) || ego projection (warps 8..15, g=2,3) ----
        if (warp < 4) {
            float4 vE = *(const float4*)&vs[lane * 4];
            float4 eg = *(const float4*)&heb[warp * 128 + lane * 4];
            float pe = eg.x * vE.x + eg.y * vE.y + eg.z * vE.z + eg.w * vE.w;
            #pragma unroll
            for (int o = 16; o > 0; o >>= 1) pe += __shfl_xor_sync(0xffffffffu, pe, o);
            float x = logit[warp * KNBR + lane] + pe;
            x = (x > 0.f) ? x : 0.2f * x;                          // leaky_relu
            x = (mskb[warp * KNBR + lane] > 0) ? x : NEG_INF;      // mask
            float mx = x;
            #pragma unroll
            for (int o = 16; o > 0; o >>= 1) mx = fmaxf(mx, __shfl_xor_sync(0xffffffffu, mx, o));
            float ee = (x == NEG_INF) ? 0.f : __expf(x - mx);
            float ss = ee;
            #pragma unroll
            for (int o = 16; o > 0; o >>= 1) ss += __shfl_xor_sync(0xffffffffu, ss, o);
            attn[warp * KNBR + lane] = (ss > 0.f) ? (ee / ss) : 0.f;
        } else if (tid >= 256) {
            // ego @ Wself^T for both pairs — independent of attention
            const unsigned long long* xbase = (const unsigned long long*)ego2;
            unsigned long long* rE = (unsigned long long*)redE;
            proj64(xbase,       wreg, d0, &rE[0 * 512 + g * 128 + e]);
            proj64(xbase + 128, wreg, d0, &rE[1 * 512 + g * 128 + e]);
        }
        __syncthreads();   // A2: attn ready

        // ---- weighted partial aggregation from HELD registers ----
        {
            const float* at = &attn[rr * KNBR + kq];
            float a0 = at[0], a1 = at[1], a2 = at[2], a3 = at[3];
            float a4 = at[4], a5 = at[5], a6 = at[6], a7 = at[7];
            float4 acc;
            acc.x = a0 * f0.x; acc.y = a0 * f0.y; acc.z = a0 * f0.z; acc.w = a0 * f0.w;
            acc.x = fmaf(a1, f1.x, acc.x); acc.y = fmaf(a1, f1.y, acc.y);
            acc.z = fmaf(a1, f1.z, acc.z); acc.w = fmaf(a1, f1.w, acc.w);
            acc.x = fmaf(a2, f2.x, acc.x); acc.y = fmaf(a2, f2.y, acc.y);
            acc.z = fmaf(a2, f2.z, acc.z); acc.w = fmaf(a2, f2.w, acc.w);
            acc.x = fmaf(a3, f3.x, acc.x); acc.y = fmaf(a3, f3.y, acc.y);
            acc.z = fmaf(a3, f3.z, acc.z); acc.w = fmaf(a3, f3.w, acc.w);
            acc.x = fmaf(a4, f4.x, acc.x); acc.y = fmaf(a4, f4.y, acc.y);
            acc.z = fmaf(a4, f4.z, acc.z); acc.w = fmaf(a4, f4.w, acc.w);
            acc.x = fmaf(a5, f5.x, acc.x); acc.y = fmaf(a5, f5.y, acc.y);
            acc.z = fmaf(a5, f5.z, acc.z); acc.w = fmaf(a5, f5.w, acc.w);
            acc.x = fmaf(a6, f6.x, acc.x); acc.y = fmaf(a6, f6.y, acc.y);
            acc.z = fmaf(a6, f6.z, acc.z); acc.w = fmaf(a6, f6.w, acc.w);
            acc.x = fmaf(a7, f7.x, acc.x); acc.y = fmaf(a7, f7.y, acc.y);
            acc.z = fmaf(a7, f7.z, acc.z); acc.w = fmaf(a7, f7.w, acc.w);
            ((float4*)redD)[warp * 32 + lane] = acc;
        }
        __syncthreads();   // A3

        // ---- reduce 4 partials per (row,dim) -> batch-packed agg2 ----
        {
            int r  = tid >> 7;        // 0..3 (row)
            int dd = tid & 127;
            const float* rb = &redD[(4 * r) * 128 + dd];
            agg2[(r >> 1) * 256 + 2 * dd + (r & 1)] =
                rb[0] + rb[128] + rb[256] + rb[384];
        }
        __syncthreads();   // A4

        // ---- msg projection: agg @ Wmsg^T (threads 0..255, g=0,1) ----
        if (tid < 256) {
            const unsigned long long* xbase = (const unsigned long long*)agg2;
            unsigned long long* rE = (unsigned long long*)redE;
            proj64(xbase,       wreg, d0, &rE[0 * 512 + g * 128 + e]);
            proj64(xbase + 128, wreg, d0, &rE[1 * 512 + g * 128 + e]);
        }
        __syncthreads();   // A5

        // ---- combine + tanh + store (256 threads: pair x dim) ----
        if (tid < 256) {
            int pr = tid >> 7, dd = tid & 127;
            const float2* r = (const float2*)redE + pr * 512;
            float2 r0 = r[0 * 128 + dd];
            float2 r1 = r[1 * 128 + dd];
            float2 r2 = r[2 * 128 + dd];
            float2 r3 = r[3 * 128 + dd];
            float o0 = tanhf(r0.x + r1.x + r2.x + r3.x + bb);
            float o1 = tanhf(r0.y + r1.y + r2.y + r3.y + bb);
            size_t row = ((size_t)4 * q + 2 * pr) * D;
            out[row + dd]     = o0;
            out[row + D + dd] = o1;
        }
    }
    cp_waitall();
}

// ---------------- launch ----------------
extern "C" void kernel_launch(void* const* d_in, const int* in_sizes, int n_in,
                              void* d_out, int out_size) {
    const float* h_ego  = (const float*)d_in[0];
    const float* h_nei  = (const float*)d_in[1];
    const int*   nmask  = (const int*)  d_in[2];
    const float* Wmsg   = (const float*)d_in[3];
    const float* Wattn  = (const float*)d_in[4];
    const float* Wself  = (const float*)d_in[5];
    const float* bself  = (const float*)d_in[6];
    float* out = (float*)d_out;

    int sms = 0;
    cudaDeviceGetAttribute(&sms, cudaDevAttrMultiProcessorCount, 0);
    if (sms <= 0) sms = 148;

    cudaFuncSetAttribute(gat_kernel, cudaFuncAttributeMaxDynamicSharedMemorySize, SMEM_BYTES);

    prep_kernel<<<1, D>>>(Wmsg, Wattn);
    gat_kernel<<<sms, T, SMEM_BYTES>>>(h_ego, h_nei, nmask, Wmsg, Wself, bself, out);
}